// round 4
// baseline (speedup 1.0000x reference)
#include <cuda_runtime.h>
#include <math.h>

// ---------------- problem constants ----------------
#define CB   128     // batch
#define CN   49      // spatial tokens
#define CIN  2048    // backbone channels
#define CG   256     // query groups
#define CD   768     // decoder dim
#define CH   8       // heads
#define CHD  96      // head dim
#define CFF  2048    // ffn dim
#define NCLS 12547
#define CDUP 50

// ---------------- scratch (device globals; no allocation allowed) ----------------
__device__ float g_mem  [CB*CN*CD];   // embedded memory (relu)
__device__ float g_k    [CB*CN*CD];
__device__ float g_v    [CB*CN*CD];
__device__ float g_tln  [CG*CD];      // LN(2*query)  (batch-independent)
__device__ float g_q    [CG*CD];      // q projection (batch-independent)
__device__ float g_attn [CB*CG*CD];   // attention output (pre o-proj)
__device__ float g_oproj[CB*CG*CD];
__device__ float g_t2   [CB*CG*CD];
__device__ float g_ff1  [CB*CG*CFF];
__device__ float g_ff2  [CB*CG*CD];
__device__ float g_h    [CB*CG*CD];

// ============================================================================
// Tiled SGEMM: C[M,N] = A[M,K] @ B[K,N] + bias[N]  (optional ReLU)
// Requires M%64==0, N%64==0, K%16==0 (true for all calls here).
// 64x64 block tile, BK=16, 256 threads, 4x4 micro-tile, float4 paths.
// ============================================================================
#define TBM 64
#define TBN 64
#define TBK 16

template<bool RELU>
__global__ __launch_bounds__(256) void sgemm_bias_kernel(
    const float* __restrict__ A, const float* __restrict__ B,
    const float* __restrict__ bias, float* __restrict__ C,
    int M, int N, int K)
{
    __shared__ float As[TBK][TBM];
    __shared__ float Bs[TBK][TBN];

    const int tid = threadIdx.x;
    const int m0  = blockIdx.y * TBM;
    const int n0  = blockIdx.x * TBN;
    const int tx  = tid & 15;       // 0..15 -> 4 cols each
    const int ty  = tid >> 4;       // 0..15 -> 4 rows each

    // A load: 64 rows x 16 k, float4 along K. thread -> (arow, acol4)
    const int arow  = tid >> 2;          // 0..63
    const int acol4 = (tid & 3) * 4;     // 0,4,8,12
    // B load: 16 k x 64 n, float4 along N
    const int brow  = tid >> 4;          // 0..15
    const int bcol4 = (tid & 15) * 4;    // 0..60

    const float* Aptr = A + (size_t)(m0 + arow) * K + acol4;
    const float* Bptr = B + (size_t)brow * N + n0 + bcol4;

    float acc[4][4] = {};

    for (int k0 = 0; k0 < K; k0 += TBK) {
        float4 av = *(const float4*)(Aptr + k0);
        As[acol4 + 0][arow] = av.x;
        As[acol4 + 1][arow] = av.y;
        As[acol4 + 2][arow] = av.z;
        As[acol4 + 3][arow] = av.w;
        *(float4*)&Bs[brow][bcol4] = *(const float4*)(Bptr + (size_t)k0 * N);
        __syncthreads();

        #pragma unroll
        for (int kk = 0; kk < TBK; kk++) {
            float4 a = *(const float4*)&As[kk][ty * 4];
            float4 b = *(const float4*)&Bs[kk][tx * 4];
            acc[0][0] += a.x * b.x; acc[0][1] += a.x * b.y; acc[0][2] += a.x * b.z; acc[0][3] += a.x * b.w;
            acc[1][0] += a.y * b.x; acc[1][1] += a.y * b.y; acc[1][2] += a.y * b.z; acc[1][3] += a.y * b.w;
            acc[2][0] += a.z * b.x; acc[2][1] += a.z * b.y; acc[2][2] += a.z * b.z; acc[2][3] += a.z * b.w;
            acc[3][0] += a.w * b.x; acc[3][1] += a.w * b.y; acc[3][2] += a.w * b.z; acc[3][3] += a.w * b.w;
        }
        __syncthreads();
    }

    const int colb = n0 + tx * 4;
    float4 bv = *(const float4*)(bias + colb);
    #pragma unroll
    for (int i = 0; i < 4; i++) {
        int row = m0 + ty * 4 + i;
        float4 c;
        c.x = acc[i][0] + bv.x;
        c.y = acc[i][1] + bv.y;
        c.z = acc[i][2] + bv.z;
        c.w = acc[i][3] + bv.w;
        if (RELU) {
            c.x = fmaxf(c.x, 0.f); c.y = fmaxf(c.y, 0.f);
            c.z = fmaxf(c.z, 0.f); c.w = fmaxf(c.w, 0.f);
        }
        *(float4*)(C + (size_t)row * N + colb) = c;
    }
}

// ============================================================================
// LayerNorm over D=768 with fused residual:  out[row] = LN(a[row] + res[row % rowmod])
// One block (256 threads) per row, 3 elements per thread.
// ============================================================================
__global__ __launch_bounds__(256) void ln_residual_kernel(
    const float* __restrict__ a, const float* __restrict__ res,
    const float* __restrict__ gamma, const float* __restrict__ beta,
    float* __restrict__ out, int rowmod)
{
    __shared__ float sh[8];
    __shared__ float s_mean, s_rstd;

    const int row = blockIdx.x;
    const int tid = threadIdx.x;
    const float* ar = a   + (size_t)row * CD;
    const float* rr = res + (size_t)(row % rowmod) * CD;

    float x[3];
    #pragma unroll
    for (int i = 0; i < 3; i++) {
        int j = tid + i * 256;
        x[i] = ar[j] + rr[j];
    }

    // mean
    float s = x[0] + x[1] + x[2];
    #pragma unroll
    for (int o = 16; o > 0; o >>= 1) s += __shfl_down_sync(0xffffffffu, s, o);
    if ((tid & 31) == 0) sh[tid >> 5] = s;
    __syncthreads();
    if (tid < 32) {
        float v = (tid < 8) ? sh[tid] : 0.f;
        #pragma unroll
        for (int o = 4; o > 0; o >>= 1) v += __shfl_down_sync(0xffffffffu, v, o);
        if (tid == 0) s_mean = v * (1.f / CD);
    }
    __syncthreads();
    const float m = s_mean;

    // variance
    float d2 = 0.f;
    #pragma unroll
    for (int i = 0; i < 3; i++) { float d = x[i] - m; d2 += d * d; }
    #pragma unroll
    for (int o = 16; o > 0; o >>= 1) d2 += __shfl_down_sync(0xffffffffu, d2, o);
    if ((tid & 31) == 0) sh[tid >> 5] = d2;
    __syncthreads();
    if (tid < 32) {
        float v = (tid < 8) ? sh[tid] : 0.f;
        #pragma unroll
        for (int o = 4; o > 0; o >>= 1) v += __shfl_down_sync(0xffffffffu, v, o);
        if (tid == 0) s_rstd = rsqrtf(v * (1.f / CD) + 1e-5f);
    }
    __syncthreads();
    const float rs = s_rstd;

    float* orow = out + (size_t)row * CD;
    #pragma unroll
    for (int i = 0; i < 3; i++) {
        int j = tid + i * 256;
        orow[j] = (x[i] - m) * rs * gamma[j] + beta[j];
    }
}

// ============================================================================
// Cross-attention. q is batch-independent [G, D]. k,v: [B, N, D]. o: [B, G, D].
// grid (H, B), 256 threads; thread t handles query group g=t for head blockIdx.x.
// N=49 scores kept in registers; K/V head slices staged in smem.
// ============================================================================
__global__ __launch_bounds__(256) void attn_kernel(
    const float* __restrict__ q, const float* __restrict__ k,
    const float* __restrict__ v, float* __restrict__ o)
{
    const int h = blockIdx.x;
    const int b = blockIdx.y;
    __shared__ float ks[CN][CHD];
    __shared__ float vs[CN][CHD];

    const int tid = threadIdx.x;
    for (int i = tid; i < CN * CHD; i += 256) {
        int n = i / CHD, d = i % CHD;
        size_t gi = (size_t)(b * CN + n) * CD + h * CHD + d;
        ks[n][d] = k[gi];
        vs[n][d] = v[gi];
    }
    __syncthreads();

    const int g = tid;
    float p[CN];
    #pragma unroll
    for (int n = 0; n < CN; n++) p[n] = 0.f;

    const float* qrow = q + (size_t)g * CD + h * CHD;
    for (int dc = 0; dc < CHD; dc += 8) {
        float q8[8];
        #pragma unroll
        for (int j = 0; j < 8; j++) q8[j] = qrow[dc + j];
        #pragma unroll
        for (int n = 0; n < CN; n++) {
            float s = 0.f;
            #pragma unroll
            for (int j = 0; j < 8; j++) s += q8[j] * ks[n][dc + j];
            p[n] += s;
        }
    }

    const float scale = rsqrtf((float)CHD);
    float mx = -1e30f;
    #pragma unroll
    for (int n = 0; n < CN; n++) { p[n] *= scale; mx = fmaxf(mx, p[n]); }
    float sum = 0.f;
    #pragma unroll
    for (int n = 0; n < CN; n++) { p[n] = expf(p[n] - mx); sum += p[n]; }
    const float inv = 1.f / sum;
    #pragma unroll
    for (int n = 0; n < CN; n++) p[n] *= inv;

    float* orow = o + (size_t)(b * CG + g) * CD + h * CHD;
    for (int d = 0; d < CHD; d++) {
        float acc = 0.f;
        #pragma unroll
        for (int n = 0; n < CN; n++) acc += p[n] * vs[n][d];
        orow[d] = acc;
    }
}

// ============================================================================
// GroupFC: logits[b, g*50+f] = h[b,g,:] . Wg[g,:,f] + bg   (clip to NUM_CLASSES)
// grid (G, B/16), block 16*50=800: thread = (bi, f)
// ============================================================================
__global__ __launch_bounds__(800) void groupfc_kernel(
    const float* __restrict__ h, const float* __restrict__ Wg,
    const float* __restrict__ bg, float* __restrict__ out)
{
    const int g   = blockIdx.x;
    const int tid = threadIdx.x;
    const int f   = tid % CDUP;
    const int bi  = tid / CDUP;           // 0..15
    const int b   = blockIdx.y * 16 + bi;

    const float* hr = h  + (size_t)(b * CG + g) * CD;
    const float* wg = Wg + (size_t)g * CD * CDUP + f;

    float acc = 0.f;
    #pragma unroll 8
    for (int d = 0; d < CD; d++)
        acc += hr[d] * wg[(size_t)d * CDUP];

    const int c = g * CDUP + f;
    if (c < NCLS)
        out[(size_t)b * NCLS + c] = acc + bg[c];
}

// ============================================================================
// Orchestration
// ============================================================================
static inline float* sym(const void* s)
{
    void* p = nullptr;
    cudaGetSymbolAddress(&p, s);
    return (float*)p;
}

extern "C" void kernel_launch(void* const* d_in, const int* in_sizes, int n_in,
                              void* d_out, int out_size)
{
    const float* x       = (const float*)d_in[0];
    const float* W_embed = (const float*)d_in[1];
    const float* b_embed = (const float*)d_in[2];
    const float* query   = (const float*)d_in[3];
    const float* Wq = (const float*)d_in[4];  const float* bq = (const float*)d_in[5];
    const float* Wk = (const float*)d_in[6];  const float* bk = (const float*)d_in[7];
    const float* Wv = (const float*)d_in[8];  const float* bv = (const float*)d_in[9];
    const float* Wo = (const float*)d_in[10]; const float* bo = (const float*)d_in[11];
    const float* g1 = (const float*)d_in[12]; const float* be1 = (const float*)d_in[13];
    const float* g2 = (const float*)d_in[14]; const float* be2 = (const float*)d_in[15];
    const float* g3 = (const float*)d_in[16]; const float* be3 = (const float*)d_in[17];
    const float* W1 = (const float*)d_in[18]; const float* b1 = (const float*)d_in[19];
    const float* W2 = (const float*)d_in[20]; const float* b2 = (const float*)d_in[21];
    const float* Wg = (const float*)d_in[22]; const float* bg = (const float*)d_in[23];
    float* out = (float*)d_out;

    float* mem   = sym(g_mem);
    float* kbuf  = sym(g_k);
    float* vbuf  = sym(g_v);
    float* tln   = sym(g_tln);
    float* qbuf  = sym(g_q);
    float* attn  = sym(g_attn);
    float* oproj = sym(g_oproj);
    float* t2    = sym(g_t2);
    float* ff1   = sym(g_ff1);
    float* ff2   = sym(g_ff2);
    float* hbuf  = sym(g_h);

    const int MBN = CB * CN;   // 6272
    const int MBG = CB * CG;   // 32768

    // 1) mem = relu(x @ W_embed + b_embed)   [6272,768] <- [6272,2048]x[2048,768]
    sgemm_bias_kernel<true><<<dim3(CD / TBN, MBN / TBM), 256>>>(
        x, W_embed, b_embed, mem, MBN, CD, CIN);

    // 2) k = mem @ Wk + bk ;  v = mem @ Wv + bv
    sgemm_bias_kernel<false><<<dim3(CD / TBN, MBN / TBM), 256>>>(
        mem, Wk, bk, kbuf, MBN, CD, CD);
    sgemm_bias_kernel<false><<<dim3(CD / TBN, MBN / TBM), 256>>>(
        mem, Wv, bv, vbuf, MBN, CD, CD);

    // 3) tln = LN(query + query) = LN(2*query)    [256,768], batch-independent
    ln_residual_kernel<<<CG, 256>>>(query, query, g1, be1, tln, CG);

    // 4) q = tln @ Wq + bq   [256,768], batch-independent
    sgemm_bias_kernel<false><<<dim3(CD / TBN, CG / TBM), 256>>>(
        tln, Wq, bq, qbuf, CG, CD, CD);

    // 5) attention -> attn [B,G,D]
    attn_kernel<<<dim3(CH, CB), 256>>>(qbuf, kbuf, vbuf, attn);

    // 6) oproj = attn @ Wo + bo   [32768,768]
    sgemm_bias_kernel<false><<<dim3(CD / TBN, MBG / TBM), 256>>>(
        attn, Wo, bo, oproj, MBG, CD, CD);

    // 7) t2 = LN(oproj + tln[g])   (residual row index = row % G)
    ln_residual_kernel<<<MBG, 256>>>(oproj, tln, g2, be2, t2, CG);

    // 8) ff1 = relu(t2 @ W1 + b1)   [32768,2048]
    sgemm_bias_kernel<true><<<dim3(CFF / TBN, MBG / TBM), 256>>>(
        t2, W1, b1, ff1, MBG, CFF, CD);

    // 9) ff2 = ff1 @ W2 + b2   [32768,768]
    sgemm_bias_kernel<false><<<dim3(CD / TBN, MBG / TBM), 256>>>(
        ff1, W2, b2, ff2, MBG, CD, CFF);

    // 10) h = LN(ff2 + t2)
    ln_residual_kernel<<<MBG, 256>>>(ff2, t2, g3, be3, hbuf, MBG);

    // 11) GroupFC -> logits [128, 12547]
    groupfc_kernel<<<dim3(CG, CB / 16), 16 * CDUP>>>(hbuf, Wg, bg, out);
}

// round 5
// speedup vs baseline: 2.7661x; 2.7661x over previous
#include <cuda_runtime.h>
#include <math.h>
#include <stdint.h>

// ---------------- problem constants ----------------
#define CB   128     // batch
#define CN   49      // spatial tokens
#define CIN  2048    // backbone channels
#define CG   256     // query groups
#define CD   768     // decoder dim
#define CH   8       // heads
#define CHD  96      // head dim
#define CFF  2048    // ffn dim
#define NCLS 12547
#define CDUP 50

// ---------------- scratch (device globals; no allocation allowed) ----------------
__device__ float g_mem  [CB*CN*CD];
__device__ float g_k    [CB*CN*CD];
__device__ float g_v    [CB*CN*CD];
__device__ float g_tln  [CG*CD];
__device__ float g_q    [CG*CD];
__device__ float g_attn [CB*CG*CD];
__device__ float g_oproj[CB*CG*CD];
__device__ float g_t2   [CB*CG*CD];
__device__ float g_ff1  [CB*CG*CFF];
__device__ float g_ff2  [CB*CG*CD];
__device__ float g_h    [CB*CG*CD];

// ============================================================================
// TF32 tensor-core GEMM: C[M,N] = A[M,K] @ B[K,N] + bias[N]  (optional ReLU)
// Requires M%128==0, N%128==0, K%16==0 (true for all calls here).
// 128x128x16 block tile, 256 threads (8 warps, 4x2), warp tile 32x64,
// mma.sync.m16n8k8.tf32, register-staged prefetch, rna-rounded tf32 inputs.
// ============================================================================
#define BM 128
#define BN 128
#define BK 16
#define ASTRIDE (BK + 4)     // 20 floats  -> conflict-free A-frag LDS
#define BSTRIDE (BN + 8)     // 136 floats -> conflict-free B-frag LDS

__device__ __forceinline__ float to_tf32(float x) {
    asm("cvt.rna.tf32.f32 %0, %0;" : "+f"(x));
    return x;
}

__device__ __forceinline__ void mma1688(float* d, const uint32_t* a, const uint32_t* b) {
    asm volatile(
        "mma.sync.aligned.m16n8k8.row.col.f32.tf32.tf32.f32 "
        "{%0,%1,%2,%3}, {%4,%5,%6,%7}, {%8,%9}, {%0,%1,%2,%3};"
        : "+f"(d[0]), "+f"(d[1]), "+f"(d[2]), "+f"(d[3])
        : "r"(a[0]), "r"(a[1]), "r"(a[2]), "r"(a[3]), "r"(b[0]), "r"(b[1]));
}

template<bool RELU>
__global__ __launch_bounds__(256, 2) void gemm_tf32_kernel(
    const float* __restrict__ A, const float* __restrict__ B,
    const float* __restrict__ bias, float* __restrict__ C,
    int M, int N, int K)
{
    __shared__ float As[BM * ASTRIDE];   // [m][k], padded
    __shared__ float Bs[BK * BSTRIDE];   // [k][n], padded

    const int tid  = threadIdx.x;
    const int lane = tid & 31;
    const int warp = tid >> 5;
    const int wm   = warp & 3;        // 4 warps along M
    const int wn   = warp >> 2;       // 2 warps along N
    const int m0   = blockIdx.y * BM;
    const int n0   = blockIdx.x * BN;

    const int g = lane >> 2;          // 0..7
    const int t = lane & 3;           // 0..3

    // gmem staging: 2 float4 each for A and B tiles
    const int i0 = tid, i1 = tid + 256;
    const int ar0 = i0 >> 2,  ac0 = (i0 & 3) * 4;
    const int ar1 = i1 >> 2,  ac1 = (i1 & 3) * 4;
    const int br0 = i0 >> 5,  bc0 = (i0 & 31) * 4;
    const int br1 = i1 >> 5,  bc1 = (i1 & 31) * 4;

    const float* Ap0 = A + (size_t)(m0 + ar0) * K + ac0;
    const float* Ap1 = A + (size_t)(m0 + ar1) * K + ac1;
    const float* Bp0 = B + (size_t)br0 * N + n0 + bc0;
    const float* Bp1 = B + (size_t)br1 * N + n0 + bc1;

    float4 ra0 = *(const float4*)Ap0;
    float4 ra1 = *(const float4*)Ap1;
    float4 rb0 = *(const float4*)Bp0;
    float4 rb1 = *(const float4*)Bp1;

    float acc[2][8][4];
    #pragma unroll
    for (int im = 0; im < 2; im++)
        #pragma unroll
        for (int in = 0; in < 8; in++)
            #pragma unroll
            for (int r = 0; r < 4; r++) acc[im][in][r] = 0.f;

    const int warp_m = wm * 32;
    const int warp_n = wn * 64;

    for (int k0 = 0; k0 < K; k0 += BK) {
        // stage -> smem with rna tf32 rounding
        {
            float4 v;
            v.x = to_tf32(ra0.x); v.y = to_tf32(ra0.y); v.z = to_tf32(ra0.z); v.w = to_tf32(ra0.w);
            *(float4*)&As[ar0 * ASTRIDE + ac0] = v;
            v.x = to_tf32(ra1.x); v.y = to_tf32(ra1.y); v.z = to_tf32(ra1.z); v.w = to_tf32(ra1.w);
            *(float4*)&As[ar1 * ASTRIDE + ac1] = v;
            v.x = to_tf32(rb0.x); v.y = to_tf32(rb0.y); v.z = to_tf32(rb0.z); v.w = to_tf32(rb0.w);
            *(float4*)&Bs[br0 * BSTRIDE + bc0] = v;
            v.x = to_tf32(rb1.x); v.y = to_tf32(rb1.y); v.z = to_tf32(rb1.z); v.w = to_tf32(rb1.w);
            *(float4*)&Bs[br1 * BSTRIDE + bc1] = v;
        }
        __syncthreads();

        // prefetch next tile while computing
        if (k0 + BK < K) {
            ra0 = *(const float4*)(Ap0 + k0 + BK);
            ra1 = *(const float4*)(Ap1 + k0 + BK);
            rb0 = *(const float4*)(Bp0 + (size_t)(k0 + BK) * N);
            rb1 = *(const float4*)(Bp1 + (size_t)(k0 + BK) * N);
        }

        #pragma unroll
        for (int kk = 0; kk < BK; kk += 8) {
            uint32_t af[2][4];
            #pragma unroll
            for (int im = 0; im < 2; im++) {
                const int r = warp_m + im * 16 + g;
                af[im][0] = __float_as_uint(As[(r    ) * ASTRIDE + kk + t    ]);
                af[im][1] = __float_as_uint(As[(r + 8) * ASTRIDE + kk + t    ]);
                af[im][2] = __float_as_uint(As[(r    ) * ASTRIDE + kk + t + 4]);
                af[im][3] = __float_as_uint(As[(r + 8) * ASTRIDE + kk + t + 4]);
            }
            uint32_t bf[8][2];
            #pragma unroll
            for (int in = 0; in < 8; in++) {
                const int c = warp_n + in * 8 + g;
                bf[in][0] = __float_as_uint(Bs[(kk + t    ) * BSTRIDE + c]);
                bf[in][1] = __float_as_uint(Bs[(kk + t + 4) * BSTRIDE + c]);
            }
            #pragma unroll
            for (int im = 0; im < 2; im++)
                #pragma unroll
                for (int in = 0; in < 8; in++)
                    mma1688(acc[im][in], af[im], bf[in]);
        }
        __syncthreads();
    }

    // epilogue: bias (+ReLU), direct to gmem
    #pragma unroll
    for (int in = 0; in < 8; in++) {
        const int c0 = n0 + warp_n + in * 8 + t * 2;
        float2 bv = *(const float2*)(bias + c0);
        #pragma unroll
        for (int im = 0; im < 2; im++) {
            const int r0 = m0 + warp_m + im * 16 + g;
            float2 o0, o1;
            o0.x = acc[im][in][0] + bv.x;
            o0.y = acc[im][in][1] + bv.y;
            o1.x = acc[im][in][2] + bv.x;
            o1.y = acc[im][in][3] + bv.y;
            if (RELU) {
                o0.x = fmaxf(o0.x, 0.f); o0.y = fmaxf(o0.y, 0.f);
                o1.x = fmaxf(o1.x, 0.f); o1.y = fmaxf(o1.y, 0.f);
            }
            *(float2*)(C + (size_t)r0 * N + c0)       = o0;
            *(float2*)(C + (size_t)(r0 + 8) * N + c0) = o1;
        }
    }
}

// ============================================================================
// LayerNorm over D=768 with fused residual: out[row] = LN(a[row] + res[row % rowmod])
// ============================================================================
__global__ __launch_bounds__(256) void ln_residual_kernel(
    const float* __restrict__ a, const float* __restrict__ res,
    const float* __restrict__ gamma, const float* __restrict__ beta,
    float* __restrict__ out, int rowmod)
{
    __shared__ float sh[8];
    __shared__ float s_mean, s_rstd;

    const int row = blockIdx.x;
    const int tid = threadIdx.x;
    const float* ar = a   + (size_t)row * CD;
    const float* rr = res + (size_t)(row % rowmod) * CD;

    float x[3];
    #pragma unroll
    for (int i = 0; i < 3; i++) {
        int j = tid + i * 256;
        x[i] = ar[j] + rr[j];
    }

    float s = x[0] + x[1] + x[2];
    #pragma unroll
    for (int o = 16; o > 0; o >>= 1) s += __shfl_down_sync(0xffffffffu, s, o);
    if ((tid & 31) == 0) sh[tid >> 5] = s;
    __syncthreads();
    if (tid < 32) {
        float v = (tid < 8) ? sh[tid] : 0.f;
        #pragma unroll
        for (int o = 4; o > 0; o >>= 1) v += __shfl_down_sync(0xffffffffu, v, o);
        if (tid == 0) s_mean = v * (1.f / CD);
    }
    __syncthreads();
    const float m = s_mean;

    float d2 = 0.f;
    #pragma unroll
    for (int i = 0; i < 3; i++) { float d = x[i] - m; d2 += d * d; }
    #pragma unroll
    for (int o = 16; o > 0; o >>= 1) d2 += __shfl_down_sync(0xffffffffu, d2, o);
    if ((tid & 31) == 0) sh[tid >> 5] = d2;
    __syncthreads();
    if (tid < 32) {
        float v = (tid < 8) ? sh[tid] : 0.f;
        #pragma unroll
        for (int o = 4; o > 0; o >>= 1) v += __shfl_down_sync(0xffffffffu, v, o);
        if (tid == 0) s_rstd = rsqrtf(v * (1.f / CD) + 1e-5f);
    }
    __syncthreads();
    const float rs = s_rstd;

    float* orow = out + (size_t)row * CD;
    #pragma unroll
    for (int i = 0; i < 3; i++) {
        int j = tid + i * 256;
        orow[j] = (x[i] - m) * rs * gamma[j] + beta[j];
    }
}

// ============================================================================
// Cross-attention. q is batch-independent [G, D]. k,v: [B, N, D]. o: [B, G, D].
// ============================================================================
__global__ __launch_bounds__(256) void attn_kernel(
    const float* __restrict__ q, const float* __restrict__ k,
    const float* __restrict__ v, float* __restrict__ o)
{
    const int h = blockIdx.x;
    const int b = blockIdx.y;
    __shared__ float ks[CN][CHD];
    __shared__ float vs[CN][CHD];

    const int tid = threadIdx.x;
    for (int i = tid; i < CN * CHD; i += 256) {
        int n = i / CHD, d = i % CHD;
        size_t gi = (size_t)(b * CN + n) * CD + h * CHD + d;
        ks[n][d] = k[gi];
        vs[n][d] = v[gi];
    }
    __syncthreads();

    const int g = tid;
    float p[CN];
    #pragma unroll
    for (int n = 0; n < CN; n++) p[n] = 0.f;

    const float* qrow = q + (size_t)g * CD + h * CHD;
    for (int dc = 0; dc < CHD; dc += 8) {
        float q8[8];
        #pragma unroll
        for (int j = 0; j < 8; j++) q8[j] = qrow[dc + j];
        #pragma unroll
        for (int n = 0; n < CN; n++) {
            float s = 0.f;
            #pragma unroll
            for (int j = 0; j < 8; j++) s += q8[j] * ks[n][dc + j];
            p[n] += s;
        }
    }

    const float scale = rsqrtf((float)CHD);
    float mx = -1e30f;
    #pragma unroll
    for (int n = 0; n < CN; n++) { p[n] *= scale; mx = fmaxf(mx, p[n]); }
    float sum = 0.f;
    #pragma unroll
    for (int n = 0; n < CN; n++) { p[n] = expf(p[n] - mx); sum += p[n]; }
    const float inv = 1.f / sum;
    #pragma unroll
    for (int n = 0; n < CN; n++) p[n] *= inv;

    float* orow = o + (size_t)(b * CG + g) * CD + h * CHD;
    for (int d = 0; d < CHD; d++) {
        float acc = 0.f;
        #pragma unroll
        for (int n = 0; n < CN; n++) acc += p[n] * vs[n][d];
        orow[d] = acc;
    }
}

// ============================================================================
// GroupFC: logits[b, g*50+f] = h[b,g,:] . Wg[g,:,f] + bg
// ============================================================================
__global__ __launch_bounds__(800) void groupfc_kernel(
    const float* __restrict__ h, const float* __restrict__ Wg,
    const float* __restrict__ bg, float* __restrict__ out)
{
    const int g   = blockIdx.x;
    const int tid = threadIdx.x;
    const int f   = tid % CDUP;
    const int bi  = tid / CDUP;
    const int b   = blockIdx.y * 16 + bi;

    const float* hr = h  + (size_t)(b * CG + g) * CD;
    const float* wg = Wg + (size_t)g * CD * CDUP + f;

    float acc = 0.f;
    #pragma unroll 8
    for (int d = 0; d < CD; d++)
        acc += hr[d] * wg[(size_t)d * CDUP];

    const int c = g * CDUP + f;
    if (c < NCLS)
        out[(size_t)b * NCLS + c] = acc + bg[c];
}

// ============================================================================
// Orchestration
// ============================================================================
static inline float* sym(const void* s)
{
    void* p = nullptr;
    cudaGetSymbolAddress(&p, s);
    return (float*)p;
}

extern "C" void kernel_launch(void* const* d_in, const int* in_sizes, int n_in,
                              void* d_out, int out_size)
{
    const float* x       = (const float*)d_in[0];
    const float* W_embed = (const float*)d_in[1];
    const float* b_embed = (const float*)d_in[2];
    const float* query   = (const float*)d_in[3];
    const float* Wq = (const float*)d_in[4];  const float* bq = (const float*)d_in[5];
    const float* Wk = (const float*)d_in[6];  const float* bk = (const float*)d_in[7];
    const float* Wv = (const float*)d_in[8];  const float* bv = (const float*)d_in[9];
    const float* Wo = (const float*)d_in[10]; const float* bo = (const float*)d_in[11];
    const float* g1 = (const float*)d_in[12]; const float* be1 = (const float*)d_in[13];
    const float* g2 = (const float*)d_in[14]; const float* be2 = (const float*)d_in[15];
    const float* g3 = (const float*)d_in[16]; const float* be3 = (const float*)d_in[17];
    const float* W1 = (const float*)d_in[18]; const float* b1 = (const float*)d_in[19];
    const float* W2 = (const float*)d_in[20]; const float* b2 = (const float*)d_in[21];
    const float* Wg = (const float*)d_in[22]; const float* bg = (const float*)d_in[23];
    float* out = (float*)d_out;

    float* mem   = sym(g_mem);
    float* kbuf  = sym(g_k);
    float* vbuf  = sym(g_v);
    float* tln   = sym(g_tln);
    float* qbuf  = sym(g_q);
    float* attn  = sym(g_attn);
    float* oproj = sym(g_oproj);
    float* t2    = sym(g_t2);
    float* ff1   = sym(g_ff1);
    float* ff2   = sym(g_ff2);
    float* hbuf  = sym(g_h);

    const int MBN = CB * CN;   // 6272  (= 49 * 128)
    const int MBG = CB * CG;   // 32768

    // 1) mem = relu(x @ W_embed + b_embed)
    gemm_tf32_kernel<true><<<dim3(CD / BN, MBN / BM), 256>>>(
        x, W_embed, b_embed, mem, MBN, CD, CIN);

    // 2) k, v projections
    gemm_tf32_kernel<false><<<dim3(CD / BN, MBN / BM), 256>>>(
        mem, Wk, bk, kbuf, MBN, CD, CD);
    gemm_tf32_kernel<false><<<dim3(CD / BN, MBN / BM), 256>>>(
        mem, Wv, bv, vbuf, MBN, CD, CD);

    // 3) tln = LN(2*query)  (batch-independent)
    ln_residual_kernel<<<CG, 256>>>(query, query, g1, be1, tln, CG);

    // 4) q = tln @ Wq + bq  (batch-independent, [256,768])
    gemm_tf32_kernel<false><<<dim3(CD / BN, CG / BM), 256>>>(
        tln, Wq, bq, qbuf, CG, CD, CD);

    // 5) attention
    attn_kernel<<<dim3(CH, CB), 256>>>(qbuf, kbuf, vbuf, attn);

    // 6) o-projection
    gemm_tf32_kernel<false><<<dim3(CD / BN, MBG / BM), 256>>>(
        attn, Wo, bo, oproj, MBG, CD, CD);

    // 7) t2 = LN(oproj + tln[g])
    ln_residual_kernel<<<MBG, 256>>>(oproj, tln, g2, be2, t2, CG);

    // 8) ff1 = relu(t2 @ W1 + b1)
    gemm_tf32_kernel<true><<<dim3(CFF / BN, MBG / BM), 256>>>(
        t2, W1, b1, ff1, MBG, CFF, CD);

    // 9) ff2 = ff1 @ W2 + b2
    gemm_tf32_kernel<false><<<dim3(CD / BN, MBG / BM), 256>>>(
        ff1, W2, b2, ff2, MBG, CD, CFF);

    // 10) h = LN(ff2 + t2)
    ln_residual_kernel<<<MBG, 256>>>(ff2, t2, g3, be3, hbuf, MBG);

    // 11) GroupFC -> logits
    groupfc_kernel<<<dim3(CG, CB / 16), 16 * CDUP>>>(hbuf, Wg, bg, out);
}